// round 1
// baseline (speedup 1.0000x reference)
#include <cuda_runtime.h>

#define HH 512
#define WW 512
#define KS 32
#define TILE 64
#define PADT 95          // TILE + KS - 1
#define SX_PITCH 96      // sX row pitch (floats)
#define SV_PITCH 97      // sV row pitch (floats) -> conflict-free column walks
#define NTHREADS 256

// reflect index (numpy 'reflect': no edge duplication)
__device__ __forceinline__ int reflect_idx(int g) {
    if (g < 0) g = -g;
    if (g >= HH) g = 2 * HH - 2 - g;
    return g;
}

__global__ void localnorm_kernel(const float* __restrict__ x,
                                 float* __restrict__ out) {
    extern __shared__ float smem[];
    float* sX  = smem;                          // [PADT][SX_PITCH] raw x tile
    float* sVS = sX  + PADT * SX_PITCH;         // [TILE][SV_PITCH] vertical sums of x
    float* sVQ = sVS + TILE * SV_PITCH;         // [TILE][SV_PITCH] vertical sums of x*x

    const int img = blockIdx.z;
    const int ty0 = blockIdx.y * TILE;
    const int tx0 = blockIdx.x * TILE;
    const int tid = threadIdx.x;

    const float* xin = x + (size_t)img * HH * WW;

    // ---- 1. load reflect-padded 95x95 tile into smem (coalesced in q) ----
    for (int idx = tid; idx < PADT * PADT; idx += NTHREADS) {
        int r = idx / PADT;
        int q = idx - r * PADT;
        int gy = reflect_idx(ty0 + r - (KS / 2));
        int gx = reflect_idx(tx0 + q - (KS / 2));
        sX[r * SX_PITCH + q] = xin[gy * WW + gx];
    }
    __syncthreads();

    // ---- 2. vertical sliding sums per column: S = sum x, Q = sum x^2 ----
    if (tid < PADT) {
        const int q = tid;
        float sS = 0.f, sQ = 0.f;
        #pragma unroll
        for (int d = 0; d < KS; d++) {
            float v = sX[d * SX_PITCH + q];
            sS += v;
            sQ += v * v;
        }
        sVS[q] = sS;
        sVQ[q] = sQ;
        for (int i = 1; i < TILE; i++) {
            float xn = sX[(i + KS - 1) * SX_PITCH + q];
            float xo = sX[(i - 1) * SX_PITCH + q];
            sS += xn - xo;
            sQ += xn * xn - xo * xo;
            sVS[i * SV_PITCH + q] = sS;
            sVQ[i * SV_PITCH + q] = sQ;
        }
    }
    __syncthreads();

    // ---- 3. horizontal sliding box sums per row, IN-PLACE over V buffers ----
    // threads [0,64) handle S rows, [64,128) handle Q rows.
    // Lane->row mapping with pitch 97 => conflict-free.
    if (tid < 2 * TILE) {
        float* V = (tid < TILE) ? sVS : sVQ;
        const int row = (tid < TILE) ? tid : (tid - TILE);
        float* Vr = V + row * SV_PITCH;
        float s = 0.f;
        #pragma unroll
        for (int d = 0; d < KS; d++) s += Vr[d];
        float prev = Vr[0];     // save original before overwrite
        Vr[0] = s;
        for (int ox = 1; ox < TILE; ox++) {
            float nxt = Vr[ox];              // original V[ox] (not yet clobbered)
            s += Vr[ox + KS - 1] - prev;     // box(ox) = box(ox-1) - V[ox-1] + V[ox+31]
            prev = nxt;
            Vr[ox] = s;
        }
    }
    __syncthreads();

    // ---- 4. finalize: mean/std/clamp, coalesced global write ----
    float* oimg = out + (size_t)img * HH * WW;
    const float inv_n = 1.f / (float)(KS * KS);
    for (int idx = tid; idx < TILE * TILE; idx += NTHREADS) {
        int oy = idx >> 6;
        int ox = idx & (TILE - 1);
        float S  = sVS[oy * SV_PITCH + ox];
        float Q  = sVQ[oy * SV_PITCH + ox];
        float xc = sX[(oy + KS / 2) * SX_PITCH + (ox + KS / 2)];
        float mean = S * inv_n;
        float msq  = Q * inv_n;
        float var  = fabsf(msq - mean * mean);
        float stdv = sqrtf(var);
        float r = (xc - mean) / (stdv + 1e-10f);
        r = fminf(fmaxf(r, -6.f), 6.f);
        oimg[(size_t)(ty0 + oy) * WW + (tx0 + ox)] = r;
    }
}

extern "C" void kernel_launch(void* const* d_in, const int* in_sizes, int n_in,
                              void* d_out, int out_size) {
    const float* x = (const float*)d_in[0];
    float* out = (float*)d_out;

    const int n_img = in_sizes[0] / (HH * WW);   // 32*3 = 96
    const int smem_bytes = (PADT * SX_PITCH + 2 * TILE * SV_PITCH) * (int)sizeof(float); // 86144

    cudaFuncSetAttribute(localnorm_kernel,
                         cudaFuncAttributeMaxDynamicSharedMemorySize, smem_bytes);

    dim3 grid(WW / TILE, HH / TILE, n_img);      // 8 x 8 x 96
    localnorm_kernel<<<grid, NTHREADS, smem_bytes>>>(x, out);
}

// round 2
// speedup vs baseline: 1.1668x; 1.1668x over previous
#include <cuda_runtime.h>

#define HH 512
#define WW 512
#define KS 32
#define PD 16                 // KS/2
#define PW 544                // padded width (index 543 computed but unused by boxes)
#define RC 8                  // rows per chunk (smem staging)
#define ROWS_PER_BLOCK 64
#define NTHREADS 544          // 17 warps; thread t <-> padded column t

__device__ __forceinline__ int reflect_idx(int g) {
    if (g < 0) g = -g;
    if (g >= HH) g = 2 * HH - 2 - g;   // numpy 'reflect' (no edge dup)
    return g;
}

__global__ __launch_bounds__(NTHREADS, 3)
void localnorm_strip(const float* __restrict__ x, float* __restrict__ out) {
    __shared__ float sS[RC][PW];      // vertical sums of x, then (in-place) prefix
    __shared__ float sQ[RC][PW];      // vertical sums of x^2, then prefix

    const int tid = threadIdx.x;
    const int img = blockIdx.y;
    const int r0  = blockIdx.x * ROWS_PER_BLOCK;
    const int gx  = reflect_idx(tid - PD);        // real column this thread samples

    const float* X = x   + (size_t)img * HH * WW;
    float*       O = out + (size_t)img * HH * WW;

    // ---- init vertical window for output row r0: rows [r0-16, r0+15] ----
    float vs = 0.f, vq = 0.f;
    #pragma unroll
    for (int d = -PD; d < PD; d++) {
        float v = X[(size_t)reflect_idx(r0 + d) * WW + gx];
        vs += v; vq += v * v;
    }

    const int lane = tid & 31;
    const int wid  = tid >> 5;
    const float inv_n = 1.f / (float)(KS * KS);

    #pragma unroll 1
    for (int chunk = 0; chunk < ROWS_PER_BLOCK / RC; chunk++) {
        const int ibase = r0 + chunk * RC;

        // ---- phase A: emit RC rows of vertical sums, slide window (registers) ----
        #pragma unroll
        for (int rr = 0; rr < RC; rr++) {
            sS[rr][tid] = vs;
            sQ[rr][tid] = vq;
            int i = ibase + rr;
            // window(i+1) = window(i) + x[i+16] - x[i-16]
            float va = X[(size_t)reflect_idx(i + PD) * WW + gx];
            float vb = X[(size_t)reflect_idx(i - PD) * WW + gx];
            vs += va - vb;
            vq += va * va - vb * vb;
        }
        __syncthreads();

        // ---- phase B: in-place inclusive prefix along width ----
        // 16 arrays (RC rows x {S,Q}) handled by warps 0..15; 17 elems/lane,
        // stride 17 (odd) -> bank-conflict-free. Two-pass to avoid a 17-reg array.
        if (wid < 2 * RC) {
            float* V = (wid & 1) ? &sQ[wid >> 1][0] : &sS[wid >> 1][0];
            const int base = lane * 17;
            float run = 0.f;
            #pragma unroll
            for (int k = 0; k < 17; k++) run += V[base + k];
            // inclusive warp scan of lane totals -> exclusive offset
            float tot = run;
            #pragma unroll
            for (int s = 1; s < 32; s <<= 1) {
                float u = __shfl_up_sync(0xffffffffu, tot, s);
                if (lane >= s) tot += u;
            }
            float acc = tot - run;                 // exclusive offset for this lane
            #pragma unroll
            for (int k = 0; k < 17; k++) {
                acc += V[base + k];
                V[base + k] = acc;
            }
        }
        __syncthreads();

        // ---- phase C: finalize RC x 512 outputs; box[j] = P[j+31] - P[j-1] ----
        #pragma unroll
        for (int k = 0; k < (RC * WW + NTHREADS - 1) / NTHREADS; k++) {
            int idx = k * NTHREADS + tid;
            if (idx < RC * WW) {
                int rr = idx >> 9;                 // / 512
                int oc = idx & (WW - 1);
                float pSh = sS[rr][oc + KS - 1];
                float pQh = sQ[rr][oc + KS - 1];
                float pSl = oc ? sS[rr][oc - 1] : 0.f;
                float pQl = oc ? sQ[rr][oc - 1] : 0.f;
                float mean = (pSh - pSl) * inv_n;
                float msq  = (pQh - pQl) * inv_n;
                float xc   = X[(size_t)(ibase + rr) * WW + oc];
                float var  = fabsf(msq - mean * mean);
                float r    = (xc - mean) / (sqrtf(var) + 1e-10f);
                r = fminf(fmaxf(r, -6.f), 6.f);
                O[(size_t)(ibase + rr) * WW + oc] = r;
            }
        }
        __syncthreads();   // protect sS/sQ before next chunk's phase A
    }
}

extern "C" void kernel_launch(void* const* d_in, const int* in_sizes, int n_in,
                              void* d_out, int out_size) {
    const float* x = (const float*)d_in[0];
    float* out = (float*)d_out;
    const int n_img = in_sizes[0] / (HH * WW);     // 96

    dim3 grid(HH / ROWS_PER_BLOCK, n_img);         // 8 x 96 = 768 blocks
    localnorm_strip<<<grid, NTHREADS>>>(x, out);
}

// round 3
// speedup vs baseline: 1.9968x; 1.7113x over previous
#include <cuda_runtime.h>

#define HH 512
#define WW 512
#define KS 32
#define PD 16            // KS/2
#define RC 8             // rows per chunk (16 scan arrays = 16 warps)
#define RPB 64           // output rows per block
#define NT 512           // one thread per real column
#define SPITCH 544       // f(c) = c + (c>>4) maps 0..511 -> 0..542; slot 543 = zero
#define ZSLOT 543

__global__ __launch_bounds__(NT, 3)
void localnorm_strip2(const float* __restrict__ x, float* __restrict__ out) {
    __shared__ float sS[RC * SPITCH];   // vertical sums of x   -> in-place prefix
    __shared__ float sQ[RC * SPITCH];   // vertical sums of x^2 -> in-place prefix

    const int tid  = threadIdx.x;
    const int lane = tid & 31;
    const int wid  = tid >> 5;
    const int r0   = blockIdx.x * RPB;

    const float* __restrict__ X = x   + (size_t)blockIdx.y * (HH * WW);
    float* __restrict__       O = out + (size_t)blockIdx.y * (HH * WW);

    // zero the "P[-1]" slot once (never touched by phases A/B)
    if (tid < 2 * RC) {
        float* p = (tid < RC) ? sS : sQ;
        p[(tid & (RC - 1)) * SPITCH + ZSLOT] = 0.f;
    }

    // ---- init vertical window: rows r0-16 .. r0+15 (only lower reflect possible) ----
    float vs = 0.f, vq = 0.f;
    #pragma unroll
    for (int d = -PD; d < PD; d++) {
        int rr = abs(r0 + d);                    // numpy 'reflect', lower edge
        float v = X[(rr << 9) + tid];
        vs += v; vq = fmaf(v, v, vq);
    }

    const int fcol = tid + (tid >> 4);           // phase-A store slot
    const float inv_n = 1.f / (float)(KS * KS);

    // ---- phase-C per-thread constants (oc == tid) ----
    const int oc  = tid;
    int hi = oc + 15; if (hi > 511) hi = 511;
    const int fhi = hi + (hi >> 4);
    const int lo  = oc - 17;
    const int flo = (lo >= 0) ? (lo + (lo >> 4)) : ZSLOT;     // P[-1] == 0
    const bool leftE  = (oc <= 15);              // window spills past column 0
    const bool rightE = (oc >= 497);             // window spills past column 511
    const int fle  = leftE  ? ((16 - oc) + ((16 - oc) >> 4)) : 0;
    const int fre2 = rightE ? ((1006 - oc) + ((1006 - oc) >> 4)) : 0;

    #pragma unroll 1
    for (int chunk = 0; chunk < RPB / RC; chunk++) {
        const int ibase = r0 + chunk * RC;

        // ---- phase A: emit RC rows of vertical sums; slide the window ----
        #pragma unroll
        for (int rr = 0; rr < RC; rr++) {
            sS[rr * SPITCH + fcol] = vs;
            sQ[rr * SPITCH + fcol] = vq;
            int i  = ibase + rr;
            int ru = i + PD; ru = (ru < HH) ? ru : (2 * HH - 2 - ru);  // upper reflect only
            int rd = abs(i - PD);                                       // lower reflect only
            float va = X[(ru << 9) + tid];
            float vb = X[(rd << 9) + tid];
            vs += va - vb;
            vq = fmaf(va, va, fmaf(-vb, vb, vq));
        }
        __syncthreads();

        // ---- phase B: 16 warps, one (row,array) each; inclusive prefix over 512 ----
        {
            float* V = ((wid & 1) ? sQ : sS) + (wid >> 1) * SPITCH + lane * 17;
            float run = 0.f;
            #pragma unroll
            for (int k = 0; k < 16; k++) run += V[k];
            float tot = run;                     // warp-scan lane totals
            #pragma unroll
            for (int s = 1; s < 32; s <<= 1) {
                float u = __shfl_up_sync(0xffffffffu, tot, s);
                if (lane >= s) tot += u;
            }
            float acc = tot - run;               // exclusive offset
            #pragma unroll
            for (int k = 0; k < 16; k++) {
                acc += V[k];
                V[k] = acc;
            }
        }
        __syncthreads();

        // ---- phase C: box[oc] = P[hi]-P[lo] (+ reflected edge terms); finalize ----
        const float* Xc = X + (ibase << 9) + tid;
        float*       Oc = O + (ibase << 9) + tid;
        #pragma unroll
        for (int rr = 0; rr < RC; rr++) {
            const float* pS = sS + rr * SPITCH;
            const float* pQ = sQ + rr * SPITCH;
            float bS = pS[fhi] - pS[flo];
            float bQ = pQ[fhi] - pQ[flo];
            if (leftE)  { bS += pS[fle] - pS[0];    bQ += pQ[fle] - pQ[0]; }
            if (rightE) { bS += pS[541] - pS[fre2]; bQ += pQ[541] - pQ[fre2]; }
            float mean = bS * inv_n;
            float msq  = bQ * inv_n;
            float xc   = Xc[rr << 9];
            float var  = fabsf(msq - mean * mean);
            float r    = (xc - mean) / (sqrtf(var) + 1e-10f);
            r = fminf(fmaxf(r, -6.f), 6.f);
            Oc[rr << 9] = r;
        }
        __syncthreads();                          // protect sS/sQ for next phase A
    }
}

extern "C" void kernel_launch(void* const* d_in, const int* in_sizes, int n_in,
                              void* d_out, int out_size) {
    const float* x = (const float*)d_in[0];
    float* out = (float*)d_out;
    const int n_img = in_sizes[0] / (HH * WW);    // 96

    dim3 grid(HH / RPB, n_img);                   // 8 x 96 = 768 blocks
    localnorm_strip2<<<grid, NT>>>(x, out);
}